// round 13
// baseline (speedup 1.0000x reference)
#include <cuda_runtime.h>
#include <cuda_bf16.h>
#include <cstdint>

#define HIDDEN    450
#define DEPTH     6
#define ATOM_FDIM 35
#define BOND_FDIM 5
#define MAX_NB    15
#define N_ATOMS   20000
#define N_BONDS   40000
#define N_MESS    16000
#define N_MOLS    1000
#define BOND_IN   (ATOM_FDIM + BOND_FDIM)   // 40
#define AIN       (ATOM_FDIM + HIDDEN)      // 485
#define N_TOTMSG  (N_MESS + N_BONDS)        // 56000

// split-bf16 geometry: A'=[Ah|Al|Ah], B'=[Bh|Bh|Bl]
#define KP     1408              // pad(3*450), 22 chunks of 64
#define KP2    1472              // pad(3*485), 23 chunks
#define KCH    64
#define WROWS  512

// ---------------- scratch (device globals; no runtime allocation) ----------
__device__ float          g_all   [(size_t)N_TOTMSG * HIDDEN]; // [tree ; msg]
__device__ float          g_binput[(size_t)N_BONDS * HIDDEN];
__device__ __nv_bfloat16  g_neiB  [(size_t)N_BONDS * KP];
__device__ __nv_bfloat16  g_WB    [(size_t)WROWS * KP];
__device__ __nv_bfloat16  g_ainB  [(size_t)N_ATOMS * KP2];
__device__ __nv_bfloat16  g_WoB   [(size_t)WROWS * KP2];
__device__ float          g_hid   [(size_t)N_ATOMS * HIDDEN];
__device__ float          g_cnt   [N_MOLS];

// ---------------- PTX helpers (baseline sm_103-legal only) ------------------
__device__ __forceinline__ uint32_t smem_u32(const void* p) {
    uint32_t a;
    asm("{ .reg .u64 t; cvta.to.shared.u64 t, %1; cvt.u32.u64 %0, t; }"
        : "=r"(a) : "l"(p));
    return a;
}
#define SWZ128(off) ((off) ^ (((off) >> 3) & 0x70))
#define CP_ASYNC16(dst, src) \
    asm volatile("cp.async.cg.shared.global [%0], [%1], 16;" :: "r"(dst), "l"(src))
#define CP_COMMIT() asm volatile("cp.async.commit_group;" ::: "memory")
#define CP_WAIT(n)  asm volatile("cp.async.wait_group %0;" :: "n"(n) : "memory")

__device__ __forceinline__ void ldsm_x4(uint32_t& r0, uint32_t& r1,
                                        uint32_t& r2, uint32_t& r3, uint32_t a) {
    asm volatile("ldmatrix.sync.aligned.m8n8.x4.shared.b16 {%0,%1,%2,%3}, [%4];"
                 : "=r"(r0), "=r"(r1), "=r"(r2), "=r"(r3) : "r"(a));
}
__device__ __forceinline__ void mma_bf16(float* d, const uint32_t* a,
                                         uint32_t b0, uint32_t b1) {
    asm volatile("mma.sync.aligned.m16n8k16.row.col.f32.bf16.bf16.f32 "
                 "{%0,%1,%2,%3}, {%4,%5,%6,%7}, {%8,%9}, {%0,%1,%2,%3};"
                 : "+f"(d[0]), "+f"(d[1]), "+f"(d[2]), "+f"(d[3])
                 : "r"(a[0]), "r"(a[1]), "r"(a[2]), "r"(a[3]), "r"(b0), "r"(b1));
}

// ---------------- HMMA split-bf16 GEMM: C = relu(A'B'^T + add) --------------
// CTA tile 128m x 256n, 256 threads = 8 warps (2x4) of 64m x 64n.
#define CHUNK_A_BYTES (128 * KCH * 2)               // 16 KB
#define CHUNK_B_BYTES (256 * KCH * 2)               // 32 KB
#define STAGE_BYTES   (CHUNK_A_BYTES + CHUNK_B_BYTES)
#define SMEM_GEMM     (2 * STAGE_BYTES)             // 96 KB

template <int KPAD, int ADDMODE>
__global__ __launch_bounds__(256)
void gemm_hmma_relu(const __nv_bfloat16* __restrict__ A,
                    const __nv_bfloat16* __restrict__ B,
                    const float* __restrict__ add,
                    float* __restrict__ C, int M)
{
    constexpr int NCH = KPAD / KCH;
    extern __shared__ char smem[];
    const uint32_t sb = smem_u32(smem);
    const int tid  = threadIdx.x;
    const int lane = tid & 31, warp = tid >> 5;
    const int wm = warp >> 2, wn = warp & 3;          // 2 x 4 warps, 64m x 64n
    const int bm = blockIdx.y * 128, n0 = blockIdx.x * 256;

    auto issue = [&](int c, int b) {
        uint32_t abase = sb + b * STAGE_BYTES;
        uint32_t bbase = abase + CHUNK_A_BYTES;
#pragma unroll
        for (int i = 0; i < 4; i++) {                 // A: 1024 float4
            int idx = tid + i * 256;
            int r = idx >> 3, q = idx & 7;
            int m = bm + r;
            uint32_t dst = abase + SWZ128((uint32_t)(r * 128 + q * 16));
            if (m < M) {
                CP_ASYNC16(dst, A + (size_t)m * KPAD + c * KCH + q * 8);
            } else {
                float4 z = make_float4(0.f, 0.f, 0.f, 0.f);
                *(float4*)(smem + (dst - sb)) = z;
            }
        }
#pragma unroll
        for (int i = 0; i < 8; i++) {                 // B: 2048 float4
            int idx = tid + i * 256;
            int r = idx >> 3, q = idx & 7;
            uint32_t dst = bbase + SWZ128((uint32_t)(r * 128 + q * 16));
            CP_ASYNC16(dst, B + (size_t)(n0 + r) * KPAD + c * KCH + q * 8);
        }
        CP_COMMIT();
    };

    float acc[4][8][4];
#pragma unroll
    for (int f = 0; f < 4; f++)
#pragma unroll
        for (int j = 0; j < 8; j++)
#pragma unroll
            for (int q = 0; q < 4; q++) acc[f][j][q] = 0.f;

    issue(0, 0);

    for (int c = 0; c < NCH; c++) {
        const int b = c & 1;
        if (c + 1 < NCH) { issue(c + 1, b ^ 1); CP_WAIT(1); }
        else             { CP_WAIT(0); }
        __syncthreads();

        const uint32_t abase = sb + b * STAGE_BYTES;
        const uint32_t bbase = abase + CHUNK_A_BYTES;
#pragma unroll
        for (int s = 0; s < 4; s++) {
            uint32_t af[4][4];
#pragma unroll
            for (int f = 0; f < 4; f++) {
                int row = wm * 64 + f * 16 + (lane & 7) + (((lane >> 3) & 1) << 3);
                int kb  = s * 32 + (((lane >> 4) & 1) << 4);
                ldsm_x4(af[f][0], af[f][1], af[f][2], af[f][3],
                        abase + SWZ128((uint32_t)(row * 128 + kb)));
            }
            uint32_t bf[8][2];
#pragma unroll
            for (int jj = 0; jj < 4; jj++) {
                int row = wn * 64 + jj * 16 + (lane & 7) + (((lane >> 4) & 1) << 3);
                int kb  = s * 32 + (((lane >> 3) & 1) << 4);
                uint32_t r0, r1, r2, r3;
                ldsm_x4(r0, r1, r2, r3, bbase + SWZ128((uint32_t)(row * 128 + kb)));
                bf[jj * 2][0] = r0;     bf[jj * 2][1] = r1;
                bf[jj * 2 + 1][0] = r2; bf[jj * 2 + 1][1] = r3;
            }
#pragma unroll
            for (int f = 0; f < 4; f++)
#pragma unroll
                for (int j = 0; j < 8; j++)
                    mma_bf16(acc[f][j], af[f], bf[j][0], bf[j][1]);
        }
        __syncthreads();
    }

#pragma unroll
    for (int f = 0; f < 4; f++) {
        int mrow = bm + wm * 64 + f * 16 + (lane >> 2);
#pragma unroll
        for (int half = 0; half < 2; half++) {
            int m = mrow + half * 8;
            if (m >= M) continue;
#pragma unroll
            for (int j = 0; j < 8; j++) {
                int n = n0 + wn * 64 + j * 8 + (lane & 3) * 2;
                if (n >= HIDDEN) continue;
                float2 ad;
                if (ADDMODE == 1) ad = *(const float2*)(add + (size_t)m * HIDDEN + n);
                else              ad = *(const float2*)(add + n);
                float2 o;
                o.x = fmaxf(acc[f][j][half * 2 + 0] + ad.x, 0.f);
                o.y = fmaxf(acc[f][j][half * 2 + 1] + ad.y, 0.f);
                *(float2*)(C + (size_t)m * HIDDEN + n) = o;
            }
        }
    }
}

// ---------------- tree -> g_all[0:N_MESS) one-time copy ----------------------
__global__ void copy_tree(const float* __restrict__ tree, float* __restrict__ all)
{
    int i = blockIdx.x * blockDim.x + threadIdx.x;   // float4 index
    const int n4 = N_MESS * HIDDEN / 4;              // 1.8M, divisible
    if (i < n4) ((float4*)all)[i] = ((const float4*)tree)[i];
}

// ---------------- W (fp32 [HIDDEN, K]) -> split-bf16 B' [Bh|Bh|Bl] ----------
template <int K, int KPAD>
__global__ void convert_W(const float* __restrict__ W, __nv_bfloat16* __restrict__ WB)
{
    int idx = blockIdx.x * blockDim.x + threadIdx.x;
    if (idx >= WROWS * KPAD) return;
    int n = idx / KPAD, k = idx % KPAD;
    __nv_bfloat16 out = __float2bfloat16(0.f);
    if (n < HIDDEN) {
        if (k < K) out = __float2bfloat16(W[(size_t)n * K + k]);
        else if (k < 2 * K) out = __float2bfloat16(W[(size_t)n * K + (k - K)]);
        else if (k < 3 * K) {
            float w = W[(size_t)n * K + (k - 2 * K)];
            float hi = __bfloat162float(__float2bfloat16(w));
            out = __float2bfloat16(w - hi);
        }
    }
    WB[idx] = out;
}

// ---------------- warp-per-bond gather-sum (32-bit offsets) -----------------
__global__ __launch_bounds__(256)
void gather_bonds(const int* __restrict__ bgraph,
                  const float* __restrict__ all,
                  __nv_bfloat16* __restrict__ neiB)
{
    const int b    = blockIdx.x * 8 + (threadIdx.x >> 5);
    const int lane = threadIdx.x & 31;

    int off = 0;
    if (lane < MAX_NB) off = bgraph[(size_t)b * MAX_NB + lane] * HIDDEN;
    int offs[MAX_NB];
#pragma unroll
    for (int k = 0; k < MAX_NB; k++)
        offs[k] = __shfl_sync(0xffffffffu, off, k);

    __nv_bfloat16* row = neiB + (size_t)b * KP;
#pragma unroll
    for (int q = 0; q < 8; q++) {
        int h2 = q * 32 + lane;
        if (h2 < HIDDEN / 2) {
            float2 s = make_float2(0.f, 0.f);
#pragma unroll
            for (int k = 0; k < MAX_NB; k++) {
                float2 v = *(const float2*)(all + offs[k] + 2 * h2);
                s.x += v.x; s.y += v.y;
            }
            __nv_bfloat16 h0 = __float2bfloat16(s.x), h1 = __float2bfloat16(s.y);
            __nv_bfloat16 l0 = __float2bfloat16(s.x - __bfloat162float(h0));
            __nv_bfloat16 l1 = __float2bfloat16(s.y - __bfloat162float(h1));
            __nv_bfloat162 hi; hi.x = h0; hi.y = h1;
            __nv_bfloat162 lo; lo.x = l0; lo.y = l1;
            *(__nv_bfloat162*)(row + 2 * h2)              = hi;
            *(__nv_bfloat162*)(row + HIDDEN + 2 * h2)     = lo;
            *(__nv_bfloat162*)(row + 2 * HIDDEN + 2 * h2) = hi;
        }
    }
    if (lane < 29) {
        __nv_bfloat162 z; z.x = __float2bfloat16(0.f); z.y = z.x;
        *(__nv_bfloat162*)(row + 3 * HIDDEN + 2 * lane) = z;
    }
}

// ---------------- warp-per-atom gather + concat -----------------------------
__global__ __launch_bounds__(256)
void gather_atoms(const int* __restrict__ agraph,
                  const float* __restrict__ fatoms,
                  const float* __restrict__ all,
                  __nv_bfloat16* __restrict__ ainB)
{
    const int a    = blockIdx.x * 8 + (threadIdx.x >> 5);
    const int lane = threadIdx.x & 31;

    int off = 0;
    if (lane < MAX_NB) off = agraph[(size_t)a * MAX_NB + lane] * HIDDEN;
    int offs[MAX_NB];
#pragma unroll
    for (int k = 0; k < MAX_NB; k++)
        offs[k] = __shfl_sync(0xffffffffu, off, k);

    __nv_bfloat16* row = ainB + (size_t)a * KP2;
#pragma unroll
    for (int p = 0; p < 2; p++) {
        int h = p * 32 + lane;
        if (h < ATOM_FDIM) {
            float v = fatoms[(size_t)a * ATOM_FDIM + h];
            __nv_bfloat16 hi = __float2bfloat16(v);
            __nv_bfloat16 lo = __float2bfloat16(v - __bfloat162float(hi));
            row[h] = hi; row[AIN + h] = lo; row[2 * AIN + h] = hi;
        }
    }
#pragma unroll
    for (int q = 0; q < 8; q++) {
        int h2 = q * 32 + lane;
        if (h2 < HIDDEN / 2) {
            float2 s = make_float2(0.f, 0.f);
#pragma unroll
            for (int k = 0; k < MAX_NB; k++) {
                float2 v = *(const float2*)(all + offs[k] + 2 * h2);
                s.x += v.x; s.y += v.y;
            }
            int h = ATOM_FDIM + 2 * h2;
            __nv_bfloat16 h0 = __float2bfloat16(s.x), h1 = __float2bfloat16(s.y);
            __nv_bfloat16 l0 = __float2bfloat16(s.x - __bfloat162float(h0));
            __nv_bfloat16 l1 = __float2bfloat16(s.y - __bfloat162float(h1));
            row[h]           = h0; row[h + 1]           = h1;
            row[AIN + h]     = l0; row[AIN + h + 1]     = l1;
            row[2 * AIN + h] = h0; row[2 * AIN + h + 1] = h1;
        }
    }
    if (lane < 17) row[3 * AIN + lane] = __float2bfloat16(0.f);
}

// ---------------- fp32 SIMT GEMM (gemm0 only: K=40) -------------------------
#define BM 128
#define BN 128
#define BK 16
#define SPITCH 132

__global__ __launch_bounds__(256, 2)
void gemm_nt0(const float* __restrict__ A, const float* __restrict__ W,
              float* __restrict__ C, float* __restrict__ C2,
              int M, int N, int K)
{
    __shared__ float sA[2][BK * SPITCH];
    __shared__ float sB[2][BK * SPITCH];
    const int bm = blockIdx.y * BM, bn = blockIdx.x * BN;
    const int tid = threadIdx.x, tx = tid & 15, ty = tid >> 4;

    float acc[8][8];
#pragma unroll
    for (int i = 0; i < 8; i++)
#pragma unroll
        for (int j = 0; j < 8; j++) acc[i][j] = 0.f;

    const int ntiles = (K + BK - 1) / BK;
    float ar[8], br[8];
#pragma unroll
    for (int i = 0; i < 8; i++) {
        int idx = tid + i * 256, r = idx >> 4, kk = idx & 15;
        int m = bm + r;
        ar[i] = (m < M && kk < K) ? A[(size_t)m * K + kk] : 0.f;
        int n = bn + r;
        br[i] = (n < N && kk < K) ? W[(size_t)n * K + kk] : 0.f;
    }
#pragma unroll
    for (int i = 0; i < 8; i++) {
        int idx = tid + i * 256, r = idx >> 4, kk = idx & 15;
        sA[0][kk * SPITCH + r] = ar[i];
        sB[0][kk * SPITCH + r] = br[i];
    }
    __syncthreads();

    int buf = 0;
    for (int t = 0; t < ntiles; t++) {
        if (t + 1 < ntiles) {
            int k0 = (t + 1) * BK;
#pragma unroll
            for (int i = 0; i < 8; i++) {
                int idx = tid + i * 256, r = idx >> 4, kk = idx & 15;
                int m = bm + r, k = k0 + kk;
                ar[i] = (m < M && k < K) ? A[(size_t)m * K + k] : 0.f;
                int n = bn + r;
                br[i] = (n < N && k < K) ? W[(size_t)n * K + k] : 0.f;
            }
        }
        const float* pa = sA[buf];
        const float* pb = sB[buf];
#pragma unroll
        for (int kk = 0; kk < BK; kk++) {
            float a_[8], b_[8];
            *(float4*)&a_[0] = *(const float4*)&pa[kk * SPITCH + ty * 8];
            *(float4*)&a_[4] = *(const float4*)&pa[kk * SPITCH + ty * 8 + 4];
            *(float4*)&b_[0] = *(const float4*)&pb[kk * SPITCH + tx * 8];
            *(float4*)&b_[4] = *(const float4*)&pb[kk * SPITCH + tx * 8 + 4];
#pragma unroll
            for (int i = 0; i < 8; i++)
#pragma unroll
                for (int j = 0; j < 8; j++) acc[i][j] += a_[i] * b_[j];
        }
        if (t + 1 < ntiles) {
            int nb = buf ^ 1;
#pragma unroll
            for (int i = 0; i < 8; i++) {
                int idx = tid + i * 256, r = idx >> 4, kk = idx & 15;
                sA[nb][kk * SPITCH + r] = ar[i];
                sB[nb][kk * SPITCH + r] = br[i];
            }
            __syncthreads();
            buf = nb;
        }
    }
#pragma unroll
    for (int i = 0; i < 8; i++) {
        int m = bm + ty * 8 + i;
        if (m >= M) break;
#pragma unroll
        for (int j = 0; j < 8; j++) {
            int n = bn + tx * 8 + j;
            if (n < N) {
                float v = acc[i][j];
                C [(size_t)m * N + n] = v;
                C2[(size_t)m * N + n] = fmaxf(v, 0.f);
            }
        }
    }
}

// ---------------- segment mean ----------------------------------------------
__global__ void zero_out(float* __restrict__ out, float* __restrict__ cnt)
{
    int i = blockIdx.x * blockDim.x + threadIdx.x;
    if (i < N_MOLS * HIDDEN) out[i] = 0.f;
    if (i < N_MOLS) cnt[i] = 0.f;
}
__global__ void count_mols(const int* __restrict__ mol_ids, float* __restrict__ cnt)
{
    int a = blockIdx.x * blockDim.x + threadIdx.x;
    if (a < N_ATOMS) atomicAdd(&cnt[mol_ids[a]], 1.f);
}
__global__ void accum_mols(const float* __restrict__ hid,
                           const int* __restrict__ mol_ids,
                           float* __restrict__ out)
{
    int a = blockIdx.x;
    int m = mol_ids[a];
    for (int h = threadIdx.x; h < HIDDEN; h += blockDim.x)
        atomicAdd(&out[(size_t)m * HIDDEN + h], hid[(size_t)a * HIDDEN + h]);
}
__global__ void divide_mols(float* __restrict__ out, const float* __restrict__ cnt)
{
    int m = blockIdx.x;
    float inv = 1.f / cnt[m];
    for (int h = threadIdx.x; h < HIDDEN; h += blockDim.x)
        out[(size_t)m * HIDDEN + h] *= inv;
}

// ---------------- launch ------------------------------------------------------
extern "C" void kernel_launch(void* const* d_in, const int* in_sizes, int n_in,
                              void* d_out, int out_size)
{
    const float *fatoms = 0, *fbonds = 0, *tree = 0, *W_i = 0, *W_h = 0, *W_o = 0, *b_o = 0;
    const int *agraph = 0, *bgraph = 0, *mol_ids = 0;
    for (int i = 0; i < n_in; i++) {
        switch (in_sizes[i]) {
            case N_ATOMS * ATOM_FDIM: fatoms  = (const float*)d_in[i]; break;
            case N_BONDS * BOND_IN:   fbonds  = (const float*)d_in[i]; break;
            case N_ATOMS * MAX_NB:    agraph  = (const int*)  d_in[i]; break;
            case N_BONDS * MAX_NB:    bgraph  = (const int*)  d_in[i]; break;
            case N_ATOMS:             mol_ids = (const int*)  d_in[i]; break;
            case N_MESS * HIDDEN:     tree    = (const float*)d_in[i]; break;
            case HIDDEN * BOND_IN:    W_i     = (const float*)d_in[i]; break;
            case HIDDEN * HIDDEN:     W_h     = (const float*)d_in[i]; break;
            case HIDDEN * AIN:        W_o     = (const float*)d_in[i]; break;
            case HIDDEN:              b_o     = (const float*)d_in[i]; break;
            default: break;
        }
    }
    float* out = (float*)d_out;

    static float *p_all = 0, *p_binput = 0, *p_hid = 0, *p_cnt = 0;
    static __nv_bfloat16 *p_neiB = 0, *p_WB = 0, *p_ainB = 0, *p_WoB = 0;
    if (!p_all) {
        cudaGetSymbolAddress((void**)&p_all,    g_all);
        cudaGetSymbolAddress((void**)&p_binput, g_binput);
        cudaGetSymbolAddress((void**)&p_neiB,   g_neiB);
        cudaGetSymbolAddress((void**)&p_WB,     g_WB);
        cudaGetSymbolAddress((void**)&p_ainB,   g_ainB);
        cudaGetSymbolAddress((void**)&p_WoB,    g_WoB);
        cudaGetSymbolAddress((void**)&p_hid,    g_hid);
        cudaGetSymbolAddress((void**)&p_cnt,    g_cnt);
        cudaFuncSetAttribute(gemm_hmma_relu<KP, 1>,
                             cudaFuncAttributeMaxDynamicSharedMemorySize, SMEM_GEMM);
        cudaFuncSetAttribute(gemm_hmma_relu<KP2, 2>,
                             cudaFuncAttributeMaxDynamicSharedMemorySize, SMEM_GEMM);
    }
    float* p_msg = p_all + (size_t)N_MESS * HIDDEN;   // msg region inside g_all

    dim3 gB((HIDDEN + BN - 1) / BN, (N_BONDS + BM - 1) / BM);  // (4, 313)
    dim3 gM(2, (N_BONDS + 127) / 128);                         // (2, 313)
    dim3 gM2(2, (N_ATOMS + 127) / 128);                        // (2, 157)

    // 0) tree -> g_all head ; weight conversions
    copy_tree<<<(N_MESS * HIDDEN / 4 + 255) / 256, 256>>>(tree, p_all);
    convert_W<HIDDEN, KP ><<<(WROWS * KP  + 255) / 256, 256>>>(W_h, p_WB);
    convert_W<AIN,    KP2><<<(WROWS * KP2 + 255) / 256, 256>>>(W_o, p_WoB);

    // 1) binput = fbonds @ W_i^T ; msg = relu(binput)  (into g_all tail)
    gemm_nt0<<<gB, 256>>>(fbonds, W_i, p_binput, p_msg, N_BONDS, HIDDEN, BOND_IN);

    // 2) DEPTH-1 message passing iterations
    for (int it = 0; it < DEPTH - 1; it++) {
        gather_bonds<<<N_BONDS / 8, 256>>>(bgraph, p_all, p_neiB);
        gemm_hmma_relu<KP, 1><<<gM, 256, SMEM_GEMM>>>(p_neiB, p_WB, p_binput,
                                                      p_msg, N_BONDS);
    }

    // 3) atom-side gather + concat
    gather_atoms<<<N_ATOMS / 8, 256>>>(agraph, fatoms, p_all, p_ainB);

    // 4) atom_hiddens = relu(ainput @ W_o^T + b_o)
    gemm_hmma_relu<KP2, 2><<<gM2, 256, SMEM_GEMM>>>(p_ainB, p_WoB, b_o,
                                                    p_hid, N_ATOMS);

    // 5) segment mean over molecules
    zero_out<<<(N_MOLS * HIDDEN + 255) / 256, 256>>>(out, p_cnt);
    count_mols<<<(N_ATOMS + 255) / 256, 256>>>(mol_ids, p_cnt);
    accum_mols<<<N_ATOMS, 128>>>(p_hid, mol_ids, out);
    divide_mols<<<N_MOLS, 128>>>(out, p_cnt);
}

// round 16
// speedup vs baseline: 1.0351x; 1.0351x over previous
#include <cuda_runtime.h>
#include <cuda_bf16.h>
#include <cstdint>

#define HIDDEN    450
#define DEPTH     6
#define ATOM_FDIM 35
#define BOND_FDIM 5
#define MAX_NB    15
#define N_ATOMS   20000
#define N_BONDS   40000
#define N_MESS    16000
#define N_MOLS    1000
#define BOND_IN   (ATOM_FDIM + BOND_FDIM)   // 40
#define AIN       (ATOM_FDIM + HIDDEN)      // 485
#define N_TOTMSG  (N_MESS + N_BONDS)        // 56000

// split-bf16 geometry: A'=[Ah|Al|Ah], B'=[Bh|Bh|Bl]
#define KP     1408              // pad(3*450), 22 chunks of 64
#define KP2    1472              // pad(3*485), 23 chunks
#define KP0    128               // pad(3*40),  2 chunks
#define KCH    64
#define WROWS  512

// ---------------- scratch (device globals; no runtime allocation) ----------
__device__ float          g_all   [(size_t)N_TOTMSG * HIDDEN]; // [tree ; msg]
__device__ float          g_binput[(size_t)N_BONDS * HIDDEN];
__device__ __nv_bfloat16  g_neiB  [(size_t)N_BONDS * KP];
__device__ __nv_bfloat16  g_WB    [(size_t)WROWS * KP];
__device__ __nv_bfloat16  g_ainB  [(size_t)N_ATOMS * KP2];
__device__ __nv_bfloat16  g_WoB   [(size_t)WROWS * KP2];
__device__ __nv_bfloat16  g_fbB   [(size_t)N_BONDS * KP0];    // split A' (fbonds)
__device__ __nv_bfloat16  g_WiB   [(size_t)WROWS * KP0];      // split B' (W_i)
__device__ float          g_hid   [(size_t)N_ATOMS * HIDDEN];
__device__ float          g_cnt   [N_MOLS];

// ---------------- PTX helpers (baseline sm_103-legal only) ------------------
__device__ __forceinline__ uint32_t smem_u32(const void* p) {
    uint32_t a;
    asm("{ .reg .u64 t; cvta.to.shared.u64 t, %1; cvt.u32.u64 %0, t; }"
        : "=r"(a) : "l"(p));
    return a;
}
#define SWZ128(off) ((off) ^ (((off) >> 3) & 0x70))
#define CP_ASYNC16(dst, src) \
    asm volatile("cp.async.cg.shared.global [%0], [%1], 16;" :: "r"(dst), "l"(src))
#define CP_COMMIT() asm volatile("cp.async.commit_group;" ::: "memory")
#define CP_WAIT(n)  asm volatile("cp.async.wait_group %0;" :: "n"(n) : "memory")

__device__ __forceinline__ void ldsm_x4(uint32_t& r0, uint32_t& r1,
                                        uint32_t& r2, uint32_t& r3, uint32_t a) {
    asm volatile("ldmatrix.sync.aligned.m8n8.x4.shared.b16 {%0,%1,%2,%3}, [%4];"
                 : "=r"(r0), "=r"(r1), "=r"(r2), "=r"(r3) : "r"(a));
}
__device__ __forceinline__ void mma_bf16(float* d, const uint32_t* a,
                                         uint32_t b0, uint32_t b1) {
    asm volatile("mma.sync.aligned.m16n8k16.row.col.f32.bf16.bf16.f32 "
                 "{%0,%1,%2,%3}, {%4,%5,%6,%7}, {%8,%9}, {%0,%1,%2,%3};"
                 : "+f"(d[0]), "+f"(d[1]), "+f"(d[2]), "+f"(d[3])
                 : "r"(a[0]), "r"(a[1]), "r"(a[2]), "r"(a[3]), "r"(b0), "r"(b1));
}

// ---------------- HMMA split-bf16 GEMM ---------------------------------------
// CTA tile 128m x 256n, 256 threads = 8 warps (2x4) of 64m x 64n.
// ADDMODE 0: C = acc, C2 = relu(acc)
// ADDMODE 1: C = relu(acc + add[m*HIDDEN+n])
// ADDMODE 2: C = relu(acc + add[n])
#define CHUNK_A_BYTES (128 * KCH * 2)               // 16 KB
#define CHUNK_B_BYTES (256 * KCH * 2)               // 32 KB
#define STAGE_BYTES   (CHUNK_A_BYTES + CHUNK_B_BYTES)
#define SMEM_GEMM     (2 * STAGE_BYTES)             // 96 KB

template <int KPAD, int ADDMODE>
__global__ __launch_bounds__(256)
void gemm_hmma_relu(const __nv_bfloat16* __restrict__ A,
                    const __nv_bfloat16* __restrict__ B,
                    const float* __restrict__ add,
                    float* __restrict__ C, float* __restrict__ C2, int M)
{
    constexpr int NCH = KPAD / KCH;
    extern __shared__ char smem[];
    const uint32_t sb = smem_u32(smem);
    const int tid  = threadIdx.x;
    const int lane = tid & 31, warp = tid >> 5;
    const int wm = warp >> 2, wn = warp & 3;          // 2 x 4 warps, 64m x 64n
    const int bm = blockIdx.y * 128, n0 = blockIdx.x * 256;

    auto issue = [&](int c, int b) {
        uint32_t abase = sb + b * STAGE_BYTES;
        uint32_t bbase = abase + CHUNK_A_BYTES;
#pragma unroll
        for (int i = 0; i < 4; i++) {                 // A: 1024 float4
            int idx = tid + i * 256;
            int r = idx >> 3, q = idx & 7;
            int m = bm + r;
            uint32_t dst = abase + SWZ128((uint32_t)(r * 128 + q * 16));
            if (m < M) {
                CP_ASYNC16(dst, A + (size_t)m * KPAD + c * KCH + q * 8);
            } else {
                float4 z = make_float4(0.f, 0.f, 0.f, 0.f);
                *(float4*)(smem + (dst - sb)) = z;
            }
        }
#pragma unroll
        for (int i = 0; i < 8; i++) {                 // B: 2048 float4
            int idx = tid + i * 256;
            int r = idx >> 3, q = idx & 7;
            uint32_t dst = bbase + SWZ128((uint32_t)(r * 128 + q * 16));
            CP_ASYNC16(dst, B + (size_t)(n0 + r) * KPAD + c * KCH + q * 8);
        }
        CP_COMMIT();
    };

    float acc[4][8][4];
#pragma unroll
    for (int f = 0; f < 4; f++)
#pragma unroll
        for (int j = 0; j < 8; j++)
#pragma unroll
            for (int q = 0; q < 4; q++) acc[f][j][q] = 0.f;

    issue(0, 0);

    for (int c = 0; c < NCH; c++) {
        const int b = c & 1;
        if (c + 1 < NCH) { issue(c + 1, b ^ 1); CP_WAIT(1); }
        else             { CP_WAIT(0); }
        __syncthreads();

        const uint32_t abase = sb + b * STAGE_BYTES;
        const uint32_t bbase = abase + CHUNK_A_BYTES;
#pragma unroll
        for (int s = 0; s < 4; s++) {
            uint32_t af[4][4];
#pragma unroll
            for (int f = 0; f < 4; f++) {
                int row = wm * 64 + f * 16 + (lane & 7) + (((lane >> 3) & 1) << 3);
                int kb  = s * 32 + (((lane >> 4) & 1) << 4);
                ldsm_x4(af[f][0], af[f][1], af[f][2], af[f][3],
                        abase + SWZ128((uint32_t)(row * 128 + kb)));
            }
            uint32_t bf[8][2];
#pragma unroll
            for (int jj = 0; jj < 4; jj++) {
                int row = wn * 64 + jj * 16 + (lane & 7) + (((lane >> 4) & 1) << 3);
                int kb  = s * 32 + (((lane >> 3) & 1) << 4);
                uint32_t r0, r1, r2, r3;
                ldsm_x4(r0, r1, r2, r3, bbase + SWZ128((uint32_t)(row * 128 + kb)));
                bf[jj * 2][0] = r0;     bf[jj * 2][1] = r1;
                bf[jj * 2 + 1][0] = r2; bf[jj * 2 + 1][1] = r3;
            }
#pragma unroll
            for (int f = 0; f < 4; f++)
#pragma unroll
                for (int j = 0; j < 8; j++)
                    mma_bf16(acc[f][j], af[f], bf[j][0], bf[j][1]);
        }
        __syncthreads();
    }

#pragma unroll
    for (int f = 0; f < 4; f++) {
        int mrow = bm + wm * 64 + f * 16 + (lane >> 2);
#pragma unroll
        for (int half = 0; half < 2; half++) {
            int m = mrow + half * 8;
            if (m >= M) continue;
#pragma unroll
            for (int j = 0; j < 8; j++) {
                int n = n0 + wn * 64 + j * 8 + (lane & 3) * 2;
                if (n >= HIDDEN) continue;
                float ax = acc[f][j][half * 2 + 0];
                float ay = acc[f][j][half * 2 + 1];
                if (ADDMODE == 0) {
                    float2 raw; raw.x = ax; raw.y = ay;
                    *(float2*)(C + (size_t)m * HIDDEN + n) = raw;
                    float2 rl; rl.x = fmaxf(ax, 0.f); rl.y = fmaxf(ay, 0.f);
                    *(float2*)(C2 + (size_t)m * HIDDEN + n) = rl;
                } else {
                    float2 ad;
                    if (ADDMODE == 1) ad = *(const float2*)(add + (size_t)m * HIDDEN + n);
                    else              ad = *(const float2*)(add + n);
                    float2 o;
                    o.x = fmaxf(ax + ad.x, 0.f);
                    o.y = fmaxf(ay + ad.y, 0.f);
                    *(float2*)(C + (size_t)m * HIDDEN + n) = o;
                }
            }
        }
    }
}

// ---------------- tree -> g_all[0:N_MESS) one-time copy ----------------------
__global__ void copy_tree(const float* __restrict__ tree, float* __restrict__ all)
{
    int i = blockIdx.x * blockDim.x + threadIdx.x;
    const int n4 = N_MESS * HIDDEN / 4;
    if (i < n4) ((float4*)all)[i] = ((const float4*)tree)[i];
}

// ---------------- W (fp32 [HIDDEN, K]) -> split-bf16 B' [Bh|Bh|Bl] ----------
template <int K, int KPAD>
__global__ void convert_W(const float* __restrict__ W, __nv_bfloat16* __restrict__ WB)
{
    int idx = blockIdx.x * blockDim.x + threadIdx.x;
    if (idx >= WROWS * KPAD) return;
    int n = idx / KPAD, k = idx % KPAD;
    __nv_bfloat16 out = __float2bfloat16(0.f);
    if (n < HIDDEN) {
        if (k < K) out = __float2bfloat16(W[(size_t)n * K + k]);
        else if (k < 2 * K) out = __float2bfloat16(W[(size_t)n * K + (k - K)]);
        else if (k < 3 * K) {
            float w = W[(size_t)n * K + (k - 2 * K)];
            float hi = __bfloat162float(__float2bfloat16(w));
            out = __float2bfloat16(w - hi);
        }
    }
    WB[idx] = out;
}

// ---------------- fbonds (fp32 [B, 40]) -> split-bf16 A' [Ah|Al|Ah] ---------
__global__ void convert_fb(const float* __restrict__ fb, __nv_bfloat16* __restrict__ out)
{
    int idx = blockIdx.x * blockDim.x + threadIdx.x;
    if (idx >= N_BONDS * KP0) return;
    int m = idx >> 7, k = idx & (KP0 - 1);
    __nv_bfloat16 v = __float2bfloat16(0.f);
    if (k < 3 * BOND_IN) {
        int kk = k % BOND_IN;
        float w = fb[(size_t)m * BOND_IN + kk];
        __nv_bfloat16 hi = __float2bfloat16(w);
        if (k >= BOND_IN && k < 2 * BOND_IN)
            v = __float2bfloat16(w - __bfloat162float(hi));   // Al
        else
            v = hi;                                           // Ah
    }
    out[idx] = v;
}

// ---------------- warp-per-bond gather-sum (32-bit offsets) -----------------
__global__ __launch_bounds__(256)
void gather_bonds(const int* __restrict__ bgraph,
                  const float* __restrict__ all,
                  __nv_bfloat16* __restrict__ neiB)
{
    const int b    = blockIdx.x * 8 + (threadIdx.x >> 5);
    const int lane = threadIdx.x & 31;

    int off = 0;
    if (lane < MAX_NB) off = bgraph[(size_t)b * MAX_NB + lane] * HIDDEN;
    int offs[MAX_NB];
#pragma unroll
    for (int k = 0; k < MAX_NB; k++)
        offs[k] = __shfl_sync(0xffffffffu, off, k);

    __nv_bfloat16* row = neiB + (size_t)b * KP;
#pragma unroll
    for (int q = 0; q < 8; q++) {
        int h2 = q * 32 + lane;
        if (h2 < HIDDEN / 2) {
            float2 s = make_float2(0.f, 0.f);
#pragma unroll
            for (int k = 0; k < MAX_NB; k++) {
                float2 v = *(const float2*)(all + offs[k] + 2 * h2);
                s.x += v.x; s.y += v.y;
            }
            __nv_bfloat16 h0 = __float2bfloat16(s.x), h1 = __float2bfloat16(s.y);
            __nv_bfloat16 l0 = __float2bfloat16(s.x - __bfloat162float(h0));
            __nv_bfloat16 l1 = __float2bfloat16(s.y - __bfloat162float(h1));
            __nv_bfloat162 hi; hi.x = h0; hi.y = h1;
            __nv_bfloat162 lo; lo.x = l0; lo.y = l1;
            *(__nv_bfloat162*)(row + 2 * h2)              = hi;
            *(__nv_bfloat162*)(row + HIDDEN + 2 * h2)     = lo;
            *(__nv_bfloat162*)(row + 2 * HIDDEN + 2 * h2) = hi;
        }
    }
    if (lane < 29) {
        __nv_bfloat162 z; z.x = __float2bfloat16(0.f); z.y = z.x;
        *(__nv_bfloat162*)(row + 3 * HIDDEN + 2 * lane) = z;
    }
}

// ---------------- warp-per-atom gather + concat -----------------------------
__global__ __launch_bounds__(256)
void gather_atoms(const int* __restrict__ agraph,
                  const float* __restrict__ fatoms,
                  const float* __restrict__ all,
                  __nv_bfloat16* __restrict__ ainB)
{
    const int a    = blockIdx.x * 8 + (threadIdx.x >> 5);
    const int lane = threadIdx.x & 31;

    int off = 0;
    if (lane < MAX_NB) off = agraph[(size_t)a * MAX_NB + lane] * HIDDEN;
    int offs[MAX_NB];
#pragma unroll
    for (int k = 0; k < MAX_NB; k++)
        offs[k] = __shfl_sync(0xffffffffu, off, k);

    __nv_bfloat16* row = ainB + (size_t)a * KP2;
#pragma unroll
    for (int p = 0; p < 2; p++) {
        int h = p * 32 + lane;
        if (h < ATOM_FDIM) {
            float v = fatoms[(size_t)a * ATOM_FDIM + h];
            __nv_bfloat16 hi = __float2bfloat16(v);
            __nv_bfloat16 lo = __float2bfloat16(v - __bfloat162float(hi));
            row[h] = hi; row[AIN + h] = lo; row[2 * AIN + h] = hi;
        }
    }
#pragma unroll
    for (int q = 0; q < 8; q++) {
        int h2 = q * 32 + lane;
        if (h2 < HIDDEN / 2) {
            float2 s = make_float2(0.f, 0.f);
#pragma unroll
            for (int k = 0; k < MAX_NB; k++) {
                float2 v = *(const float2*)(all + offs[k] + 2 * h2);
                s.x += v.x; s.y += v.y;
            }
            int h = ATOM_FDIM + 2 * h2;
            __nv_bfloat16 h0 = __float2bfloat16(s.x), h1 = __float2bfloat16(s.y);
            __nv_bfloat16 l0 = __float2bfloat16(s.x - __bfloat162float(h0));
            __nv_bfloat16 l1 = __float2bfloat16(s.y - __bfloat162float(h1));
            row[h]           = h0; row[h + 1]           = h1;
            row[AIN + h]     = l0; row[AIN + h + 1]     = l1;
            row[2 * AIN + h] = h0; row[2 * AIN + h + 1] = h1;
        }
    }
    if (lane < 17) row[3 * AIN + lane] = __float2bfloat16(0.f);
}

// ---------------- segment mean ----------------------------------------------
__global__ void zero_out(float* __restrict__ out, float* __restrict__ cnt)
{
    int i = blockIdx.x * blockDim.x + threadIdx.x;
    if (i < N_MOLS * HIDDEN) out[i] = 0.f;
    if (i < N_MOLS) cnt[i] = 0.f;
}
__global__ void count_mols(const int* __restrict__ mol_ids, float* __restrict__ cnt)
{
    int a = blockIdx.x * blockDim.x + threadIdx.x;
    if (a < N_ATOMS) atomicAdd(&cnt[mol_ids[a]], 1.f);
}
__global__ void accum_mols(const float* __restrict__ hid,
                           const int* __restrict__ mol_ids,
                           float* __restrict__ out)
{
    int a = blockIdx.x;
    int m = mol_ids[a];
    for (int h = threadIdx.x; h < HIDDEN; h += blockDim.x)
        atomicAdd(&out[(size_t)m * HIDDEN + h], hid[(size_t)a * HIDDEN + h]);
}
__global__ void divide_mols(float* __restrict__ out, const float* __restrict__ cnt)
{
    int m = blockIdx.x;
    float inv = 1.f / cnt[m];
    for (int h = threadIdx.x; h < HIDDEN; h += blockDim.x)
        out[(size_t)m * HIDDEN + h] *= inv;
}

// ---------------- launch ------------------------------------------------------
extern "C" void kernel_launch(void* const* d_in, const int* in_sizes, int n_in,
                              void* d_out, int out_size)
{
    const float *fatoms = 0, *fbonds = 0, *tree = 0, *W_i = 0, *W_h = 0, *W_o = 0, *b_o = 0;
    const int *agraph = 0, *bgraph = 0, *mol_ids = 0;
    for (int i = 0; i < n_in; i++) {
        switch (in_sizes[i]) {
            case N_ATOMS * ATOM_FDIM: fatoms  = (const float*)d_in[i]; break;
            case N_BONDS * BOND_IN:   fbonds  = (const float*)d_in[i]; break;
            case N_ATOMS * MAX_NB:    agraph  = (const int*)  d_in[i]; break;
            case N_BONDS * MAX_NB:    bgraph  = (const int*)  d_in[i]; break;
            case N_ATOMS:             mol_ids = (const int*)  d_in[i]; break;
            case N_MESS * HIDDEN:     tree    = (const float*)d_in[i]; break;
            case HIDDEN * BOND_IN:    W_i     = (const float*)d_in[i]; break;
            case HIDDEN * HIDDEN:     W_h     = (const float*)d_in[i]; break;
            case HIDDEN * AIN:        W_o     = (const float*)d_in[i]; break;
            case HIDDEN:              b_o     = (const float*)d_in[i]; break;
            default: break;
        }
    }
    float* out = (float*)d_out;

    static float *p_all = 0, *p_binput = 0, *p_hid = 0, *p_cnt = 0;
    static __nv_bfloat16 *p_neiB = 0, *p_WB = 0, *p_ainB = 0, *p_WoB = 0,
                         *p_fbB = 0, *p_WiB = 0;
    if (!p_all) {
        cudaGetSymbolAddress((void**)&p_all,    g_all);
        cudaGetSymbolAddress((void**)&p_binput, g_binput);
        cudaGetSymbolAddress((void**)&p_neiB,   g_neiB);
        cudaGetSymbolAddress((void**)&p_WB,     g_WB);
        cudaGetSymbolAddress((void**)&p_ainB,   g_ainB);
        cudaGetSymbolAddress((void**)&p_WoB,    g_WoB);
        cudaGetSymbolAddress((void**)&p_fbB,    g_fbB);
        cudaGetSymbolAddress((void**)&p_WiB,    g_WiB);
        cudaGetSymbolAddress((void**)&p_hid,    g_hid);
        cudaGetSymbolAddress((void**)&p_cnt,    g_cnt);
        cudaFuncSetAttribute(gemm_hmma_relu<KP, 1>,
                             cudaFuncAttributeMaxDynamicSharedMemorySize, SMEM_GEMM);
        cudaFuncSetAttribute(gemm_hmma_relu<KP2, 2>,
                             cudaFuncAttributeMaxDynamicSharedMemorySize, SMEM_GEMM);
        cudaFuncSetAttribute(gemm_hmma_relu<KP0, 0>,
                             cudaFuncAttributeMaxDynamicSharedMemorySize, SMEM_GEMM);
    }
    float* p_msg = p_all + (size_t)N_MESS * HIDDEN;   // msg region inside g_all

    dim3 gM (2, (N_BONDS + 127) / 128);               // (2, 313)
    dim3 gM2(2, (N_ATOMS + 127) / 128);               // (2, 157)

    // 0) tree -> g_all head ; operand conversions
    copy_tree<<<(N_MESS * HIDDEN / 4 + 255) / 256, 256>>>(tree, p_all);
    convert_W<HIDDEN, KP ><<<(WROWS * KP  + 255) / 256, 256>>>(W_h, p_WB);
    convert_W<AIN,    KP2><<<(WROWS * KP2 + 255) / 256, 256>>>(W_o, p_WoB);
    convert_W<BOND_IN, KP0><<<(WROWS * KP0 + 255) / 256, 256>>>(W_i, p_WiB);
    convert_fb<<<(N_BONDS * KP0 + 255) / 256, 256>>>(fbonds, p_fbB);

    // 1) binput = fbonds @ W_i^T ; msg = relu(binput)   (HMMA, dual store)
    gemm_hmma_relu<KP0, 0><<<gM, 256, SMEM_GEMM>>>(p_fbB, p_WiB, nullptr,
                                                   p_binput, p_msg, N_BONDS);

    // 2) DEPTH-1 message passing iterations
    for (int it = 0; it < DEPTH - 1; it++) {
        gather_bonds<<<N_BONDS / 8, 256>>>(bgraph, p_all, p_neiB);
        gemm_hmma_relu<KP, 1><<<gM, 256, SMEM_GEMM>>>(p_neiB, p_WB, p_binput,
                                                      p_msg, nullptr, N_BONDS);
    }

    // 3) atom-side gather + concat
    gather_atoms<<<N_ATOMS / 8, 256>>>(agraph, fatoms, p_all, p_ainB);

    // 4) atom_hiddens = relu(ainput @ W_o^T + b_o)
    gemm_hmma_relu<KP2, 2><<<gM2, 256, SMEM_GEMM>>>(p_ainB, p_WoB, b_o,
                                                    p_hid, nullptr, N_ATOMS);

    // 5) segment mean over molecules
    zero_out<<<(N_MOLS * HIDDEN + 255) / 256, 256>>>(out, p_cnt);
    count_mols<<<(N_ATOMS + 255) / 256, 256>>>(mol_ids, p_cnt);
    accum_mols<<<N_ATOMS, 128>>>(p_hid, mol_ids, out);
    divide_mols<<<N_MOLS, 128>>>(out, p_cnt);
}